// round 1
// baseline (speedup 1.0000x reference)
#include <cuda_runtime.h>
#include <cuda_bf16.h>
#include <cstddef>

// Problem constants
#define B  32
#define S  2048
#define F  512
#define MOMENTUM 0.1f
#define EPS 1e-5f

// ---------------- device scratch (static, no allocations) ----------------
__device__ float g_xn   [(size_t)B * S * F];   // 128 MB  centered input
__device__ float g_sigma[(size_t)B * F * F];   // 32 MB   blended covariance
__device__ float g_P    [(size_t)B * F * F];
__device__ float g_Q    [(size_t)B * F * F];
__device__ float g_T1   [(size_t)B * F * F];
__device__ float g_T2   [(size_t)B * F * F];
__device__ float g_mean [B * F];
__device__ float g_invtr[B];
__device__ float g_rstr [B];

// ---------------- kernel 1: blended mean ----------------
// m[b][f] = (1-M)*running_mean[f] + M * mean_s x[b,s,f]
__global__ void mean_kernel(const float* __restrict__ x,
                            const float* __restrict__ rm,
                            float* __restrict__ mean) {
    int b = blockIdx.x;
    int f = threadIdx.x;
    const float* xb = x + (size_t)b * S * F + f;
    float acc = 0.f;
    #pragma unroll 8
    for (int s = 0; s < S; s++) acc += xb[(size_t)s * F];
    mean[b * F + f] = (1.f - MOMENTUM) * rm[f] + MOMENTUM * (acc * (1.f / (float)S));
}

// ---------------- kernel 2: xn = x - m ----------------
__global__ void xn_kernel(const float* __restrict__ x,
                          const float* __restrict__ mean,
                          float* __restrict__ xn) {
    size_t p4 = (size_t)blockIdx.x * blockDim.x + threadIdx.x;   // float4 index
    size_t p  = p4 * 4;
    int b = (int)(p >> 20);            // S*F = 2^20
    int f = (int)(p & (F - 1));
    float4 xv = *(const float4*)(x + p);
    float4 mv = *(const float4*)(mean + b * F + f);
    float4 o;
    o.x = xv.x - mv.x; o.y = xv.y - mv.y; o.z = xv.z - mv.z; o.w = xv.w - mv.w;
    *(float4*)(xn + p) = o;
}

// ---------------- kernel 3: sigma = 0.9*rc + 0.1*(xn^T xn /(S-1) + eps*I) ----------------
// C[i,j] = sum_k A[k,i]*A[k,j], A = xn[b] (S x F). 128x128 tile, 8x8/thread, BK=8.
__global__ __launch_bounds__(256) void syrk_sigma_kernel(
        const float* __restrict__ xn,
        const float* __restrict__ rc,
        float* __restrict__ sigma) {
    __shared__ float sA[8][128];
    __shared__ float sB[8][128];
    int bz = blockIdx.z;
    const float* A = xn + (size_t)bz * S * F;
    float* C = sigma + (size_t)bz * F * F;

    int tid = threadIdx.x;
    int tx = tid & 15, ty = tid >> 4;
    int i0 = blockIdx.y * 128, j0 = blockIdx.x * 128;

    int lRow  = tid >> 5;          // 0..7
    int lCol4 = (tid & 31) * 4;    // 0..124

    float acc[8][8];
    #pragma unroll
    for (int u = 0; u < 8; u++)
        #pragma unroll
        for (int v = 0; v < 8; v++) acc[u][v] = 0.f;

    for (int k0 = 0; k0 < S; k0 += 8) {
        // both tiles loaded row-wise (k major), fully coalesced
        float4 va = *(const float4*)(A + (size_t)(k0 + lRow) * F + i0 + lCol4);
        float4 vb = *(const float4*)(A + (size_t)(k0 + lRow) * F + j0 + lCol4);
        *(float4*)&sA[lRow][lCol4] = va;
        *(float4*)&sB[lRow][lCol4] = vb;
        __syncthreads();
        #pragma unroll
        for (int kk = 0; kk < 8; kk++) {
            float4 a0 = *(const float4*)&sA[kk][ty * 8];
            float4 a1 = *(const float4*)&sA[kk][ty * 8 + 4];
            float4 b0 = *(const float4*)&sB[kk][tx * 8];
            float4 b1 = *(const float4*)&sB[kk][tx * 8 + 4];
            float ar[8] = {a0.x,a0.y,a0.z,a0.w,a1.x,a1.y,a1.z,a1.w};
            float br[8] = {b0.x,b0.y,b0.z,b0.w,b1.x,b1.y,b1.z,b1.w};
            #pragma unroll
            for (int u = 0; u < 8; u++)
                #pragma unroll
                for (int v = 0; v < 8; v++) acc[u][v] += ar[u] * br[v];
        }
        __syncthreads();
    }

    const float inv_nm1 = 1.f / (float)(S - 1);
    #pragma unroll
    for (int u = 0; u < 8; u++) {
        int i = i0 + ty * 8 + u;
        #pragma unroll
        for (int v = 0; v < 8; v++) {
            int j = j0 + tx * 8 + v;
            float sr = acc[u][v] * inv_nm1 + ((i == j) ? EPS : 0.f);
            acc[u][v] = (1.f - MOMENTUM) * rc[(size_t)i * F + j] + MOMENTUM * sr;
        }
        // store row (two float4)
        float4 o0 = make_float4(acc[u][0], acc[u][1], acc[u][2], acc[u][3]);
        float4 o1 = make_float4(acc[u][4], acc[u][5], acc[u][6], acc[u][7]);
        *(float4*)(C + (size_t)i * F + j0 + tx * 8)     = o0;
        *(float4*)(C + (size_t)i * F + j0 + tx * 8 + 4) = o1;
    }
}

// ---------------- kernel 4: trace, 1/tr, 1/sqrt(tr) ----------------
__global__ void trace_kernel(const float* __restrict__ sigma,
                             float* __restrict__ invtr,
                             float* __restrict__ rstr) {
    __shared__ float red[512];
    int b = blockIdx.x, t = threadIdx.x;
    red[t] = sigma[(size_t)b * F * F + (size_t)t * (F + 1)];
    __syncthreads();
    for (int s = 256; s > 0; s >>= 1) {
        if (t < s) red[t] += red[t + s];
        __syncthreads();
    }
    if (t == 0) {
        float tr = red[0];
        invtr[b] = 1.f / tr;
        rstr[b]  = 1.f / sqrtf(tr);
    }
}

// ---------------- kernel 5: P1 = 1.5*I - 0.5*sigma/tr (NS iteration 1 closed form) ----------------
__global__ void initp_kernel(const float* __restrict__ sigma,
                             const float* __restrict__ invtr,
                             float* __restrict__ P) {
    size_t idx = (size_t)blockIdx.x * blockDim.x + threadIdx.x;
    int b = (int)(idx >> 18);                       // F*F = 2^18
    int r = (int)((idx >> 9) & (F - 1));
    int c = (int)(idx & (F - 1));
    float v = -0.5f * invtr[b] * sigma[idx];
    if (r == c) v += 1.5f;
    P[idx] = v;
}

// ---------------- batched NN GEMM, N=K=512 fixed ----------------
// mode 0: C = A@B
// mode 1: C = 1.5*D - 0.5*scale[b]*(A@B)      (NS update, scale=1/tr)
// mode 2: C = scale[b]*(A@B)                  (final output, scale=1/sqrt(tr))
__global__ __launch_bounds__(256) void gemm_nn_kernel(
        const float* __restrict__ Ag, const float* __restrict__ Bg,
        float* __restrict__ Cg, const float* __restrict__ Dg,
        const float* __restrict__ scale,
        int mode, size_t sAb, size_t sBb, size_t sCb) {
    __shared__ float sA[8][132];   // transposed A tile, +4 pad
    __shared__ float sB[8][128];
    int bz = blockIdx.z;
    const float* A = Ag + (size_t)bz * sAb;
    const float* Bm = Bg + (size_t)bz * sBb;
    float* C = Cg + (size_t)bz * sCb;

    int tid = threadIdx.x;
    int tx = tid & 15, ty = tid >> 4;
    int m0 = blockIdx.y * 128, n0 = blockIdx.x * 128;

    int aRow = tid >> 1;             // 0..127
    int aK4  = (tid & 1) * 4;        // 0 or 4
    int bRow = tid >> 5;             // 0..7
    int bCol4 = (tid & 31) * 4;      // 0..124

    float acc[8][8];
    #pragma unroll
    for (int u = 0; u < 8; u++)
        #pragma unroll
        for (int v = 0; v < 8; v++) acc[u][v] = 0.f;

    for (int k0 = 0; k0 < F; k0 += 8) {
        float4 va = *(const float4*)(A + (size_t)(m0 + aRow) * F + k0 + aK4);
        sA[aK4 + 0][aRow] = va.x;
        sA[aK4 + 1][aRow] = va.y;
        sA[aK4 + 2][aRow] = va.z;
        sA[aK4 + 3][aRow] = va.w;
        float4 vb = *(const float4*)(Bm + (size_t)(k0 + bRow) * F + n0 + bCol4);
        *(float4*)&sB[bRow][bCol4] = vb;
        __syncthreads();
        #pragma unroll
        for (int kk = 0; kk < 8; kk++) {
            float4 a0 = *(const float4*)&sA[kk][ty * 8];
            float4 a1 = *(const float4*)&sA[kk][ty * 8 + 4];
            float4 b0 = *(const float4*)&sB[kk][tx * 8];
            float4 b1 = *(const float4*)&sB[kk][tx * 8 + 4];
            float ar[8] = {a0.x,a0.y,a0.z,a0.w,a1.x,a1.y,a1.z,a1.w};
            float br[8] = {b0.x,b0.y,b0.z,b0.w,b1.x,b1.y,b1.z,b1.w};
            #pragma unroll
            for (int u = 0; u < 8; u++)
                #pragma unroll
                for (int v = 0; v < 8; v++) acc[u][v] += ar[u] * br[v];
        }
        __syncthreads();
    }

    float sc = 0.f;
    if (mode == 1) sc = -0.5f * scale[bz];
    else if (mode == 2) sc = scale[bz];

    const float* D = (mode == 1) ? (Dg + (size_t)bz * sCb) : nullptr;

    #pragma unroll
    for (int u = 0; u < 8; u++) {
        size_t row = (size_t)(m0 + ty * 8 + u);
        size_t off = row * F + n0 + tx * 8;
        float o[8];
        if (mode == 0) {
            #pragma unroll
            for (int v = 0; v < 8; v++) o[v] = acc[u][v];
        } else if (mode == 1) {
            #pragma unroll
            for (int v = 0; v < 8; v++) o[v] = 1.5f * D[off + v] + sc * acc[u][v];
        } else {
            #pragma unroll
            for (int v = 0; v < 8; v++) o[v] = sc * acc[u][v];
        }
        *(float4*)(C + off)     = make_float4(o[0], o[1], o[2], o[3]);
        *(float4*)(C + off + 4) = make_float4(o[4], o[5], o[6], o[7]);
    }
}

// ---------------- host launcher ----------------
extern "C" void kernel_launch(void* const* d_in, const int* in_sizes, int n_in,
                              void* d_out, int out_size) {
    const float* x  = (const float*)d_in[0];
    const float* rm = (const float*)d_in[1];
    const float* rc = (const float*)d_in[2];
    float* out = (float*)d_out;

    float *xn, *sigma, *P, *Q, *T1, *T2, *mean, *invtr, *rstr;
    cudaGetSymbolAddress((void**)&xn,    g_xn);
    cudaGetSymbolAddress((void**)&sigma, g_sigma);
    cudaGetSymbolAddress((void**)&P,     g_P);
    cudaGetSymbolAddress((void**)&Q,     g_Q);
    cudaGetSymbolAddress((void**)&T1,    g_T1);
    cudaGetSymbolAddress((void**)&T2,    g_T2);
    cudaGetSymbolAddress((void**)&mean,  g_mean);
    cudaGetSymbolAddress((void**)&invtr, g_invtr);
    cudaGetSymbolAddress((void**)&rstr,  g_rstr);

    const size_t FF = (size_t)F * F;          // 262144
    const size_t SF = (size_t)S * F;          // 1048576

    // 1. blended mean
    mean_kernel<<<B, F>>>(x, rm, mean);
    // 2. xn = x - m
    xn_kernel<<<(unsigned)((size_t)B * SF / 4 / 256), 256>>>(x, mean, xn);
    // 3. sigma
    syrk_sigma_kernel<<<dim3(4, 4, B), 256>>>(xn, rc, sigma);
    // 4. trace
    trace_kernel<<<B, F>>>(sigma, invtr, rstr);
    // 5. NS iteration 1 closed form
    initp_kernel<<<(unsigned)((size_t)B * FF / 256), 256>>>(sigma, invtr, P);

    // 6. NS iterations 2..4 (ping-pong P <-> Q)
    float* Pin = P;
    float* Pout = Q;
    for (int it = 0; it < 3; it++) {
        gemm_nn_kernel<<<dim3(4, 4, B), 256>>>(Pin, Pin, T1, nullptr, nullptr, 0, FF, FF, FF);
        gemm_nn_kernel<<<dim3(4, 4, B), 256>>>(T1, Pin, T2, nullptr, nullptr, 0, FF, FF, FF);
        gemm_nn_kernel<<<dim3(4, 4, B), 256>>>(T2, sigma, Pout, Pin, invtr, 1, FF, FF, FF);
        float* tmp = Pin; Pin = Pout; Pout = tmp;
    }

    // 7. out = (xn @ P) * rsqrt(tr)
    gemm_nn_kernel<<<dim3(4, 16, B), 256>>>(xn, Pin, out, nullptr, rstr, 2, SF, FF, SF);
}

// round 2
// speedup vs baseline: 1.3611x; 1.3611x over previous
#include <cuda_runtime.h>
#include <cuda_bf16.h>
#include <cstdint>
#include <cstddef>

// Problem constants
#define B  32
#define S  2048
#define F  512
#define MOMENTUM 0.1f
#define EPS 1e-5f

// ---------------- device scratch (static, no allocations) ----------------
__device__ float g_xn   [(size_t)B * S * F];   // 128 MB  centered input
__device__ float g_sigma[(size_t)B * F * F];   // 32 MB   blended covariance
__device__ float g_P    [(size_t)B * F * F];
__device__ float g_Q    [(size_t)B * F * F];
__device__ float g_T1   [(size_t)B * F * F];
__device__ float g_T2   [(size_t)B * F * F];
__device__ float g_mean [B * F];
__device__ float g_invtr[B];
__device__ float g_rstr [B];

// ---------------- kernel 1: blended mean ----------------
__global__ void mean_kernel(const float* __restrict__ x,
                            const float* __restrict__ rm,
                            float* __restrict__ mean) {
    int b = blockIdx.x;
    int f = threadIdx.x;
    const float* xb = x + (size_t)b * S * F + f;
    float acc = 0.f;
    #pragma unroll 8
    for (int s = 0; s < S; s++) acc += xb[(size_t)s * F];
    mean[b * F + f] = (1.f - MOMENTUM) * rm[f] + MOMENTUM * (acc * (1.f / (float)S));
}

// ---------------- kernel 2: xn = x - m ----------------
__global__ void xn_kernel(const float* __restrict__ x,
                          const float* __restrict__ mean,
                          float* __restrict__ xn) {
    size_t p4 = (size_t)blockIdx.x * blockDim.x + threadIdx.x;
    size_t p  = p4 * 4;
    int b = (int)(p >> 20);            // S*F = 2^20
    int f = (int)(p & (F - 1));
    float4 xv = *(const float4*)(x + p);
    float4 mv = *(const float4*)(mean + b * F + f);
    float4 o;
    o.x = xv.x - mv.x; o.y = xv.y - mv.y; o.z = xv.z - mv.z; o.w = xv.w - mv.w;
    *(float4*)(xn + p) = o;
}

// ---------------- kernel 3: trace, 1/tr, 1/sqrt(tr) ----------------
__global__ void trace_kernel(const float* __restrict__ sigma,
                             float* __restrict__ invtr,
                             float* __restrict__ rstr) {
    __shared__ float red[512];
    int b = blockIdx.x, t = threadIdx.x;
    red[t] = sigma[(size_t)b * F * F + (size_t)t * (F + 1)];
    __syncthreads();
    for (int s = 256; s > 0; s >>= 1) {
        if (t < s) red[t] += red[t + s];
        __syncthreads();
    }
    if (t == 0) {
        float tr = red[0];
        invtr[b] = 1.f / tr;
        rstr[b]  = 1.f / sqrtf(tr);
    }
}

// ---------------- kernel 4: P1 = 1.5*I - 0.5*sigma/tr ----------------
__global__ void initp_kernel(const float* __restrict__ sigma,
                             const float* __restrict__ invtr,
                             float* __restrict__ P) {
    size_t idx = (size_t)blockIdx.x * blockDim.x + threadIdx.x;
    int b = (int)(idx >> 18);                       // F*F = 2^18
    int r = (int)((idx >> 9) & (F - 1));
    int c = (int)(idx & (F - 1));
    float v = -0.5f * invtr[b] * sigma[idx];
    if (r == c) v += 1.5f;
    P[idx] = v;
}

// ---------------- tf32 helpers ----------------
__device__ __forceinline__ void split_tf32(float x, float& h, float& l) {
    uint32_t uh;
    asm("cvt.rna.tf32.f32 %0, %1;" : "=r"(uh) : "f"(x));
    float hf = __uint_as_float(uh);
    float lf = x - hf;
    uint32_t ul;
    asm("cvt.rna.tf32.f32 %0, %1;" : "=r"(ul) : "f"(lf));
    h = hf;
    l = __uint_as_float(ul);
}

__device__ __forceinline__ void mma_tf32(float* c, const float* a, const float* b) {
    asm volatile(
        "mma.sync.aligned.m16n8k8.row.col.f32.tf32.tf32.f32 "
        "{%0,%1,%2,%3}, {%4,%5,%6,%7}, {%8,%9}, {%0,%1,%2,%3};"
        : "+f"(c[0]), "+f"(c[1]), "+f"(c[2]), "+f"(c[3])
        : "r"(__float_as_uint(a[0])), "r"(__float_as_uint(a[1])),
          "r"(__float_as_uint(a[2])), "r"(__float_as_uint(a[3])),
          "r"(__float_as_uint(b[0])), "r"(__float_as_uint(b[1])));
}

// ---------------- unified tensor-core GEMM (3xTF32) ----------------
// C[M,N] = A @ B (A: MxK row-major, or transA: A global is KxM row-major)
// mode 0: C = AB
// mode 1: C = 1.5*D - 0.5*scale[b]*AB          (NS update)
// mode 2: C = scale[b]*AB                      (final whitening output)
// mode 3: C = 0.9*E + 0.1*(AB/(S-1) + eps*I)   (sigma; E has no batch stride)
// Tiles: block 128x128x32, 8 warps (2x4), warp 64x32, mma m16n8k8.
#define SA_LD 36
#define SB_LD 132
#define SA_SZ (128 * SA_LD)
#define SB_SZ (32 * SB_LD)
#define GEMM_SMEM_BYTES ((2 * SA_SZ + 2 * SB_SZ) * 4)

__global__ __launch_bounds__(256, 2) void gemm_tf32_kernel(
        const float* __restrict__ Ag, const float* __restrict__ Bg,
        float* __restrict__ Cg, const float* __restrict__ Dg,
        const float* __restrict__ Eg, const float* __restrict__ scale,
        int M, int N, int K, int transA, int mode,
        size_t sAb, size_t sBb, size_t sCb) {
    extern __shared__ float smem[];
    float* sAh = smem;
    float* sAl = sAh + SA_SZ;
    float* sBh = sAl + SA_SZ;
    float* sBl = sBh + SB_SZ;

    int bz = blockIdx.z;
    const float* A = Ag + (size_t)bz * sAb;
    const float* Bm = Bg + (size_t)bz * sBb;
    float* C = Cg + (size_t)bz * sCb;

    int tid  = threadIdx.x;
    int lane = tid & 31;
    int wid  = tid >> 5;
    int warp_m = (wid >> 2) * 64;     // 0 or 64
    int warp_n = (wid & 3) * 32;      // 0,32,64,96
    int g  = lane >> 2;               // 0..7
    int tg = lane & 3;                // 0..3

    int m0 = blockIdx.y * 128;
    int n0 = blockIdx.x * 128;

    float acc[4][4][4];
    #pragma unroll
    for (int i = 0; i < 4; i++)
        #pragma unroll
        for (int j = 0; j < 4; j++)
            #pragma unroll
            for (int q = 0; q < 4; q++) acc[i][j][q] = 0.f;

    for (int k0 = 0; k0 < K; k0 += 32) {
        // ---- stage A tile ----
        if (!transA) {
            #pragma unroll
            for (int p = 0; p < 4; p++) {
                int r = (tid >> 3) + p * 32;
                int c = (tid & 7) * 4;
                float4 v = *(const float4*)(A + (size_t)(m0 + r) * K + k0 + c);
                float h, l;
                split_tf32(v.x, h, l); sAh[r * SA_LD + c + 0] = h; sAl[r * SA_LD + c + 0] = l;
                split_tf32(v.y, h, l); sAh[r * SA_LD + c + 1] = h; sAl[r * SA_LD + c + 1] = l;
                split_tf32(v.z, h, l); sAh[r * SA_LD + c + 2] = h; sAl[r * SA_LD + c + 2] = l;
                split_tf32(v.w, h, l); sAh[r * SA_LD + c + 3] = h; sAl[r * SA_LD + c + 3] = l;
            }
        } else {
            // A global is KxM row-major (row stride M); store transposed
            #pragma unroll
            for (int p = 0; p < 4; p++) {
                int kr = tid >> 3;                   // 0..31
                int m4 = (tid & 7) * 4 + p * 32;     // 0..124
                float4 v = *(const float4*)(A + (size_t)(k0 + kr) * M + m0 + m4);
                float h, l;
                split_tf32(v.x, h, l); sAh[(m4 + 0) * SA_LD + kr] = h; sAl[(m4 + 0) * SA_LD + kr] = l;
                split_tf32(v.y, h, l); sAh[(m4 + 1) * SA_LD + kr] = h; sAl[(m4 + 1) * SA_LD + kr] = l;
                split_tf32(v.z, h, l); sAh[(m4 + 2) * SA_LD + kr] = h; sAl[(m4 + 2) * SA_LD + kr] = l;
                split_tf32(v.w, h, l); sAh[(m4 + 3) * SA_LD + kr] = h; sAl[(m4 + 3) * SA_LD + kr] = l;
            }
        }
        // ---- stage B tile (always KxN row-major, row stride N) ----
        #pragma unroll
        for (int p = 0; p < 4; p++) {
            int kr = tid >> 3;
            int n4 = (tid & 7) * 4 + p * 32;
            float4 v = *(const float4*)(Bm + (size_t)(k0 + kr) * N + n0 + n4);
            float h, l;
            split_tf32(v.x, h, l); sBh[kr * SB_LD + n4 + 0] = h; sBl[kr * SB_LD + n4 + 0] = l;
            split_tf32(v.y, h, l); sBh[kr * SB_LD + n4 + 1] = h; sBl[kr * SB_LD + n4 + 1] = l;
            split_tf32(v.z, h, l); sBh[kr * SB_LD + n4 + 2] = h; sBl[kr * SB_LD + n4 + 2] = l;
            split_tf32(v.w, h, l); sBh[kr * SB_LD + n4 + 3] = h; sBl[kr * SB_LD + n4 + 3] = l;
        }
        __syncthreads();

        // ---- compute: 4 k-steps of 8 ----
        #pragma unroll
        for (int kk = 0; kk < 32; kk += 8) {
            // B fragments for this warp (4 n-tiles)
            float bh[4][2], bl[4][2];
            #pragma unroll
            for (int j = 0; j < 4; j++) {
                int col = warp_n + j * 8 + g;
                bh[j][0] = sBh[(kk + tg) * SB_LD + col];
                bh[j][1] = sBh[(kk + tg + 4) * SB_LD + col];
                bl[j][0] = sBl[(kk + tg) * SB_LD + col];
                bl[j][1] = sBl[(kk + tg + 4) * SB_LD + col];
            }
            #pragma unroll
            for (int i = 0; i < 4; i++) {
                int row = warp_m + i * 16;
                float ah[4], al[4];
                ah[0] = sAh[(row + g) * SA_LD + kk + tg];
                ah[1] = sAh[(row + g + 8) * SA_LD + kk + tg];
                ah[2] = sAh[(row + g) * SA_LD + kk + tg + 4];
                ah[3] = sAh[(row + g + 8) * SA_LD + kk + tg + 4];
                al[0] = sAl[(row + g) * SA_LD + kk + tg];
                al[1] = sAl[(row + g + 8) * SA_LD + kk + tg];
                al[2] = sAl[(row + g) * SA_LD + kk + tg + 4];
                al[3] = sAl[(row + g + 8) * SA_LD + kk + tg + 4];
                #pragma unroll
                for (int j = 0; j < 4; j++) {
                    mma_tf32(acc[i][j], ah, bh[j]);   // hi*hi
                    mma_tf32(acc[i][j], ah, bl[j]);   // hi*lo
                    mma_tf32(acc[i][j], al, bh[j]);   // lo*hi
                }
            }
        }
        __syncthreads();
    }

    // ---- epilogue ----
    float sc = 0.f;
    if (mode == 1) sc = -0.5f * scale[bz];
    else if (mode == 2) sc = scale[bz];
    const float* D = (mode == 1) ? (Dg + (size_t)bz * sCb) : nullptr;
    const float inv_nm1 = 1.f / (float)(S - 1);

    #pragma unroll
    for (int i = 0; i < 4; i++) {
        #pragma unroll
        for (int j = 0; j < 4; j++) {
            int r0 = m0 + warp_m + i * 16 + g;
            int c0 = n0 + warp_n + j * 8 + 2 * tg;
            #pragma unroll
            for (int half = 0; half < 2; half++) {
                int r = r0 + half * 8;
                float v0 = acc[i][j][half * 2 + 0];
                float v1 = acc[i][j][half * 2 + 1];
                size_t off = (size_t)r * N + c0;
                float2 o;
                if (mode == 0) {
                    o.x = v0; o.y = v1;
                } else if (mode == 1) {
                    o.x = 1.5f * D[off] + sc * v0;
                    o.y = 1.5f * D[off + 1] + sc * v1;
                } else if (mode == 2) {
                    o.x = sc * v0; o.y = sc * v1;
                } else {
                    float s0 = v0 * inv_nm1 + ((r == c0)     ? EPS : 0.f);
                    float s1 = v1 * inv_nm1 + ((r == c0 + 1) ? EPS : 0.f);
                    o.x = (1.f - MOMENTUM) * Eg[off] + MOMENTUM * s0;
                    o.y = (1.f - MOMENTUM) * Eg[off + 1] + MOMENTUM * s1;
                }
                *(float2*)(C + off) = o;
            }
        }
    }
}

// ---------------- host launcher ----------------
extern "C" void kernel_launch(void* const* d_in, const int* in_sizes, int n_in,
                              void* d_out, int out_size) {
    const float* x  = (const float*)d_in[0];
    const float* rm = (const float*)d_in[1];
    const float* rc = (const float*)d_in[2];
    float* out = (float*)d_out;

    float *xn, *sigma, *P, *Q, *T1, *T2, *mean, *invtr, *rstr;
    cudaGetSymbolAddress((void**)&xn,    g_xn);
    cudaGetSymbolAddress((void**)&sigma, g_sigma);
    cudaGetSymbolAddress((void**)&P,     g_P);
    cudaGetSymbolAddress((void**)&Q,     g_Q);
    cudaGetSymbolAddress((void**)&T1,    g_T1);
    cudaGetSymbolAddress((void**)&T2,    g_T2);
    cudaGetSymbolAddress((void**)&mean,  g_mean);
    cudaGetSymbolAddress((void**)&invtr, g_invtr);
    cudaGetSymbolAddress((void**)&rstr,  g_rstr);

    static bool attr_set = false;
    if (!attr_set) {
        cudaFuncSetAttribute(gemm_tf32_kernel,
                             cudaFuncAttributeMaxDynamicSharedMemorySize,
                             GEMM_SMEM_BYTES);
        attr_set = true;
    }

    const size_t FF = (size_t)F * F;          // 262144
    const size_t SF = (size_t)S * F;          // 1048576

    // 1. blended mean
    mean_kernel<<<B, F>>>(x, rm, mean);
    // 2. xn = x - m
    xn_kernel<<<(unsigned)((size_t)B * SF / 4 / 256), 256>>>(x, mean, xn);
    // 3. sigma = 0.9*rc + 0.1*(xn^T xn /(S-1) + eps*I)   [transA SYRK, K=S]
    gemm_tf32_kernel<<<dim3(4, 4, B), 256, GEMM_SMEM_BYTES>>>(
        xn, xn, sigma, nullptr, rc, nullptr,
        F, F, S, 1, 3, SF, SF, FF);
    // 4. trace
    trace_kernel<<<B, F>>>(sigma, invtr, rstr);
    // 5. NS iteration 1 closed form
    initp_kernel<<<(unsigned)((size_t)B * FF / 256), 256>>>(sigma, invtr, P);

    // 6. NS iterations 2..4 (ping-pong P <-> Q)
    float* Pin = P;
    float* Pout = Q;
    for (int it = 0; it < 3; it++) {
        gemm_tf32_kernel<<<dim3(4, 4, B), 256, GEMM_SMEM_BYTES>>>(
            Pin, Pin, T1, nullptr, nullptr, nullptr,
            F, F, F, 0, 0, FF, FF, FF);
        gemm_tf32_kernel<<<dim3(4, 4, B), 256, GEMM_SMEM_BYTES>>>(
            T1, Pin, T2, nullptr, nullptr, nullptr,
            F, F, F, 0, 0, FF, FF, FF);
        gemm_tf32_kernel<<<dim3(4, 4, B), 256, GEMM_SMEM_BYTES>>>(
            T2, sigma, Pout, Pin, nullptr, invtr,
            F, F, F, 0, 1, FF, FF, FF);
        float* tmp = Pin; Pin = Pout; Pout = tmp;
    }

    // 7. out = (xn @ P) * rsqrt(tr)
    gemm_tf32_kernel<<<dim3(4, 16, B), 256, GEMM_SMEM_BYTES>>>(
        xn, Pin, out, nullptr, nullptr, rstr,
        S, F, F, 0, 2, SF, FF, SF);
}

// round 3
// speedup vs baseline: 1.6105x; 1.1833x over previous
#include <cuda_runtime.h>
#include <cuda_bf16.h>
#include <cstdint>
#include <cstddef>

// Problem constants
#define B  32
#define S  2048
#define F  512
#define MOMENTUM 0.1f
#define EPS 1e-5f

// ---------------- device scratch (static, no allocations) ----------------
__device__ float g_xn   [(size_t)B * S * F];   // 128 MB  centered input
__device__ float g_sigma[(size_t)B * F * F];   // 32 MB   blended covariance
__device__ float g_P    [(size_t)B * F * F];
__device__ float g_Q    [(size_t)B * F * F];
__device__ float g_T1   [(size_t)B * F * F];
__device__ float g_T2   [(size_t)B * F * F];
__device__ float g_mean [B * F];
__device__ float g_invtr[B];
__device__ float g_rstr [B];

// ---------------- kernel 1: blended mean ----------------
__global__ void mean_kernel(const float* __restrict__ x,
                            const float* __restrict__ rm,
                            float* __restrict__ mean) {
    int b = blockIdx.x;
    int f = threadIdx.x;
    const float* xb = x + (size_t)b * S * F + f;
    float acc = 0.f;
    #pragma unroll 8
    for (int s = 0; s < S; s++) acc += xb[(size_t)s * F];
    mean[b * F + f] = (1.f - MOMENTUM) * rm[f] + MOMENTUM * (acc * (1.f / (float)S));
}

// ---------------- kernel 2: xn = x - m ----------------
__global__ void xn_kernel(const float* __restrict__ x,
                          const float* __restrict__ mean,
                          float* __restrict__ xn) {
    size_t p4 = (size_t)blockIdx.x * blockDim.x + threadIdx.x;
    size_t p  = p4 * 4;
    int b = (int)(p >> 20);            // S*F = 2^20
    int f = (int)(p & (F - 1));
    float4 xv = *(const float4*)(x + p);
    float4 mv = *(const float4*)(mean + b * F + f);
    float4 o;
    o.x = xv.x - mv.x; o.y = xv.y - mv.y; o.z = xv.z - mv.z; o.w = xv.w - mv.w;
    *(float4*)(xn + p) = o;
}

// ---------------- kernel 3: trace, 1/tr, 1/sqrt(tr) ----------------
__global__ void trace_kernel(const float* __restrict__ sigma,
                             float* __restrict__ invtr,
                             float* __restrict__ rstr) {
    __shared__ float red[512];
    int b = blockIdx.x, t = threadIdx.x;
    red[t] = sigma[(size_t)b * F * F + (size_t)t * (F + 1)];
    __syncthreads();
    for (int s = 256; s > 0; s >>= 1) {
        if (t < s) red[t] += red[t + s];
        __syncthreads();
    }
    if (t == 0) {
        float tr = red[0];
        invtr[b] = 1.f / tr;
        rstr[b]  = 1.f / sqrtf(tr);
    }
}

// ---------------- kernel 4: P1 = 1.5*I - 0.5*sigma/tr ----------------
__global__ void initp_kernel(const float* __restrict__ sigma,
                             const float* __restrict__ invtr,
                             float* __restrict__ P) {
    size_t idx = (size_t)blockIdx.x * blockDim.x + threadIdx.x;
    int b = (int)(idx >> 18);                       // F*F = 2^18
    int r = (int)((idx >> 9) & (F - 1));
    int c = (int)(idx & (F - 1));
    float v = -0.5f * invtr[b] * sigma[idx];
    if (r == c) v += 1.5f;
    P[idx] = v;
}

// ---------------- tf32 helpers ----------------
__device__ __forceinline__ void split_tf32(float x, float& h, float& l) {
    uint32_t uh;
    asm("cvt.rna.tf32.f32 %0, %1;" : "=r"(uh) : "f"(x));
    float hf = __uint_as_float(uh);
    float lf = x - hf;
    uint32_t ul;
    asm("cvt.rna.tf32.f32 %0, %1;" : "=r"(ul) : "f"(lf));
    h = hf;
    l = __uint_as_float(ul);
}

__device__ __forceinline__ void mma_tf32(float* c, const float* a, const float* b) {
    asm volatile(
        "mma.sync.aligned.m16n8k8.row.col.f32.tf32.tf32.f32 "
        "{%0,%1,%2,%3}, {%4,%5,%6,%7}, {%8,%9}, {%0,%1,%2,%3};"
        : "+f"(c[0]), "+f"(c[1]), "+f"(c[2]), "+f"(c[3])
        : "r"(__float_as_uint(a[0])), "r"(__float_as_uint(a[1])),
          "r"(__float_as_uint(a[2])), "r"(__float_as_uint(a[3])),
          "r"(__float_as_uint(b[0])), "r"(__float_as_uint(b[1])));
}

__device__ __forceinline__ void cp_async16(void* smem_dst, const void* gmem_src) {
    uint32_t s = (uint32_t)__cvta_generic_to_shared(smem_dst);
    asm volatile("cp.async.cg.shared.global [%0], [%1], 16;\n"
                 :: "r"(s), "l"(gmem_src));
}
#define CP_COMMIT asm volatile("cp.async.commit_group;" ::: "memory")
#define CP_WAIT1  asm volatile("cp.async.wait_group 1;"  ::: "memory")
#define CP_WAIT0  asm volatile("cp.async.wait_group 0;"  ::: "memory")

// ---------------- pipelined 3xTF32 GEMM ----------------
// C[M,N] = A @ B. TRANSA: A global is KxM (row-major). TRI: triangular grid
// over 128-blocks with mirror stores (C symmetric).
// mode 0: C = AB
// mode 1: C = 1.5*D - 0.5*scale[b]*AB          (NS update; D symmetric)
// mode 2: C = scale[b]*AB                      (final whitening output)
// mode 3: C = 0.9*E + 0.1*(AB/(S-1) + eps*I)   (sigma; E symmetric, no batch stride)
// Tiles: block 128x128x32, 8 warps (2x4), warp 64x32, mma m16n8k8. fp32 smem,
// split to tf32 hi/lo in registers. Double-buffered cp.async staging.
#define A_STG 4608          // floats per A stage: max(128*36, 32*132)
#define B_STG 4224          // 32*132
#define STG   (A_STG + B_STG)
#define GEMM_SMEM_BYTES (2 * STG * 4)

template<int TRANSA, int TRI>
__global__ __launch_bounds__(256) void gemm_tf32_pipe(
        const float* __restrict__ Ag, const float* __restrict__ Bg,
        float* __restrict__ Cg, const float* __restrict__ Dg,
        const float* __restrict__ Eg, const float* __restrict__ scale,
        int M, int N, int K, int mode,
        size_t sAb, size_t sBb, size_t sCb) {
    extern __shared__ float smem[];

    int bz = blockIdx.z;
    const float* A = Ag + (size_t)bz * sAb;
    const float* Bm = Bg + (size_t)bz * sBb;
    float* C = Cg + (size_t)bz * sCb;

    int m0, n0;
    bool mirror = false;
    if (TRI) {
        int t = blockIdx.x;   // 0..9
        int bi = (t < 4) ? 0 : (t < 7) ? 1 : (t < 9) ? 2 : 3;
        int start = (bi == 0) ? 0 : (bi == 1) ? 4 : (bi == 2) ? 7 : 9;
        int bj = bi + (t - start);
        m0 = bi * 128; n0 = bj * 128;
        mirror = (bi != bj);
    } else {
        m0 = blockIdx.y * 128;
        n0 = blockIdx.x * 128;
    }

    int tid  = threadIdx.x;
    int lane = tid & 31;
    int wid  = tid >> 5;
    int warp_m = (wid >> 2) * 64;     // 0 or 64
    int warp_n = (wid & 3) * 32;      // 0,32,64,96
    int g  = lane >> 2;               // 0..7
    int tg = lane & 3;                // 0..3

    float acc[4][4][4];
    #pragma unroll
    for (int i = 0; i < 4; i++)
        #pragma unroll
        for (int j = 0; j < 4; j++)
            #pragma unroll
            for (int q = 0; q < 4; q++) acc[i][j][q] = 0.f;

    // ---- staging lambda (cp.async, 8 x 16B per thread per stage) ----
    auto prefetch = [&](int stage, int k0) {
        float* sA = smem + stage * STG;
        float* sB = sA + A_STG;
        if (!TRANSA) {
            // A: MxK row-major -> sA[m][k], LD 36
            #pragma unroll
            for (int p = 0; p < 4; p++) {
                int c = tid + p * 256;          // chunk id 0..1023
                int m = c >> 3;
                int kc = (c & 7) * 4;
                cp_async16(sA + m * 36 + kc,
                           A + (size_t)(m0 + m) * K + k0 + kc);
            }
        } else {
            // A: KxM row-major -> sA[k][m], LD 132
            #pragma unroll
            for (int p = 0; p < 4; p++) {
                int c = tid + p * 256;
                int k = c >> 5;
                int mc = (c & 31) * 4;
                cp_async16(sA + k * 132 + mc,
                           A + (size_t)(k0 + k) * M + m0 + mc);
            }
        }
        // B: KxN row-major -> sB[k][n], LD 132
        #pragma unroll
        for (int p = 0; p < 4; p++) {
            int c = tid + p * 256;
            int k = c >> 5;
            int nc = (c & 31) * 4;
            cp_async16(sB + k * 132 + nc,
                       Bm + (size_t)(k0 + k) * N + n0 + nc);
        }
    };

    prefetch(0, 0);
    CP_COMMIT;

    int stage = 0;
    for (int k0 = 0; k0 < K; k0 += 32) {
        bool last = (k0 + 32 >= K);
        if (!last) { prefetch(stage ^ 1, k0 + 32); CP_COMMIT; }
        if (!last) { CP_WAIT1; } else { CP_WAIT0; }
        __syncthreads();

        const float* sA = smem + stage * STG;
        const float* sB = sA + A_STG;

        #pragma unroll
        for (int kk = 0; kk < 32; kk += 8) {
            // B fragments: load fp32, split in regs
            float bh[4][2], bl[4][2];
            #pragma unroll
            for (int j = 0; j < 4; j++) {
                int col = warp_n + j * 8 + g;
                float f0 = sB[(kk + tg) * 132 + col];
                float f1 = sB[(kk + tg + 4) * 132 + col];
                split_tf32(f0, bh[j][0], bl[j][0]);
                split_tf32(f1, bh[j][1], bl[j][1]);
            }
            #pragma unroll
            for (int i = 0; i < 4; i++) {
                int row = warp_m + i * 16;
                float a0, a1, a2, a3;
                if (!TRANSA) {
                    a0 = sA[(row + g) * 36 + kk + tg];
                    a1 = sA[(row + g + 8) * 36 + kk + tg];
                    a2 = sA[(row + g) * 36 + kk + tg + 4];
                    a3 = sA[(row + g + 8) * 36 + kk + tg + 4];
                } else {
                    a0 = sA[(kk + tg) * 132 + row + g];
                    a1 = sA[(kk + tg) * 132 + row + g + 8];
                    a2 = sA[(kk + tg + 4) * 132 + row + g];
                    a3 = sA[(kk + tg + 4) * 132 + row + g + 8];
                }
                float ah[4], al[4];
                split_tf32(a0, ah[0], al[0]);
                split_tf32(a1, ah[1], al[1]);
                split_tf32(a2, ah[2], al[2]);
                split_tf32(a3, ah[3], al[3]);
                #pragma unroll
                for (int j = 0; j < 4; j++) {
                    mma_tf32(acc[i][j], ah, bh[j]);   // hi*hi
                    mma_tf32(acc[i][j], ah, bl[j]);   // hi*lo
                    mma_tf32(acc[i][j], al, bh[j]);   // lo*hi
                }
            }
        }
        __syncthreads();
        stage ^= 1;
    }

    // ---- epilogue ----
    float sc = 0.f;
    if (mode == 1) sc = -0.5f * scale[bz];
    else if (mode == 2) sc = scale[bz];
    const float* D = (mode == 1) ? (Dg + (size_t)bz * sCb) : nullptr;
    const float inv_nm1 = 1.f / (float)(S - 1);

    #pragma unroll
    for (int i = 0; i < 4; i++) {
        #pragma unroll
        for (int j = 0; j < 4; j++) {
            int r0 = m0 + warp_m + i * 16 + g;
            int c0 = n0 + warp_n + j * 8 + 2 * tg;
            #pragma unroll
            for (int half = 0; half < 2; half++) {
                int r = r0 + half * 8;
                float v0 = acc[i][j][half * 2 + 0];
                float v1 = acc[i][j][half * 2 + 1];
                size_t off = (size_t)r * N + c0;
                float2 o;
                if (mode == 0) {
                    o.x = v0; o.y = v1;
                } else if (mode == 1) {
                    o.x = 1.5f * D[off] + sc * v0;
                    o.y = 1.5f * D[off + 1] + sc * v1;
                } else if (mode == 2) {
                    o.x = sc * v0; o.y = sc * v1;
                } else {
                    float s0 = v0 * inv_nm1 + ((r == c0)     ? EPS : 0.f);
                    float s1 = v1 * inv_nm1 + ((r == c0 + 1) ? EPS : 0.f);
                    o.x = (1.f - MOMENTUM) * Eg[off] + MOMENTUM * s0;
                    o.y = (1.f - MOMENTUM) * Eg[off + 1] + MOMENTUM * s1;
                }
                *(float2*)(C + off) = o;
                if (TRI && mirror) {
                    // C symmetric: same values at transposed coords
                    C[(size_t)c0 * N + r]       = o.x;
                    C[(size_t)(c0 + 1) * N + r] = o.y;
                }
            }
        }
    }
}

// ---------------- host launcher ----------------
extern "C" void kernel_launch(void* const* d_in, const int* in_sizes, int n_in,
                              void* d_out, int out_size) {
    const float* x  = (const float*)d_in[0];
    const float* rm = (const float*)d_in[1];
    const float* rc = (const float*)d_in[2];
    float* out = (float*)d_out;

    float *xn, *sigma, *P, *Q, *T1, *T2, *mean, *invtr, *rstr;
    cudaGetSymbolAddress((void**)&xn,    g_xn);
    cudaGetSymbolAddress((void**)&sigma, g_sigma);
    cudaGetSymbolAddress((void**)&P,     g_P);
    cudaGetSymbolAddress((void**)&Q,     g_Q);
    cudaGetSymbolAddress((void**)&T1,    g_T1);
    cudaGetSymbolAddress((void**)&T2,    g_T2);
    cudaGetSymbolAddress((void**)&mean,  g_mean);
    cudaGetSymbolAddress((void**)&invtr, g_invtr);
    cudaGetSymbolAddress((void**)&rstr,  g_rstr);

    static bool attr_set = false;
    if (!attr_set) {
        cudaFuncSetAttribute(gemm_tf32_pipe<0,0>,
            cudaFuncAttributeMaxDynamicSharedMemorySize, GEMM_SMEM_BYTES);
        cudaFuncSetAttribute(gemm_tf32_pipe<0,1>,
            cudaFuncAttributeMaxDynamicSharedMemorySize, GEMM_SMEM_BYTES);
        cudaFuncSetAttribute(gemm_tf32_pipe<1,1>,
            cudaFuncAttributeMaxDynamicSharedMemorySize, GEMM_SMEM_BYTES);
        attr_set = true;
    }

    const size_t FF = (size_t)F * F;          // 262144
    const size_t SF = (size_t)S * F;          // 1048576

    // 1. blended mean
    mean_kernel<<<B, F>>>(x, rm, mean);
    // 2. xn = x - m
    xn_kernel<<<(unsigned)((size_t)B * SF / 4 / 256), 256>>>(x, mean, xn);
    // 3. sigma = 0.9*rc + 0.1*(xn^T xn /(S-1) + eps*I)  [transA SYRK, triangular]
    gemm_tf32_pipe<1,1><<<dim3(10, 1, B), 256, GEMM_SMEM_BYTES>>>(
        xn, xn, sigma, nullptr, rc, nullptr,
        F, F, S, 3, SF, SF, FF);
    // 4. trace
    trace_kernel<<<B, F>>>(sigma, invtr, rstr);
    // 5. NS iteration 1 closed form
    initp_kernel<<<(unsigned)((size_t)B * FF / 256), 256>>>(sigma, invtr, P);

    // 6. NS iterations 2..4 (all products symmetric: polynomials in sigma commute)
    float* Pin = P;
    float* Pout = Q;
    for (int it = 0; it < 3; it++) {
        gemm_tf32_pipe<0,1><<<dim3(10, 1, B), 256, GEMM_SMEM_BYTES>>>(
            Pin, Pin, T1, nullptr, nullptr, nullptr,
            F, F, F, 0, FF, FF, FF);
        gemm_tf32_pipe<0,1><<<dim3(10, 1, B), 256, GEMM_SMEM_BYTES>>>(
            T1, Pin, T2, nullptr, nullptr, nullptr,
            F, F, F, 0, FF, FF, FF);
        gemm_tf32_pipe<0,1><<<dim3(10, 1, B), 256, GEMM_SMEM_BYTES>>>(
            T2, sigma, Pout, Pin, nullptr, invtr,
            F, F, F, 1, FF, FF, FF);
        float* tmp = Pin; Pin = Pout; Pout = tmp;
    }

    // 7. out = (xn @ P) * rsqrt(tr)   [full grid]
    gemm_tf32_pipe<0,0><<<dim3(4, 16, B), 256, GEMM_SMEM_BYTES>>>(
        xn, Pin, out, nullptr, nullptr, rstr,
        S, F, F, 2, SF, FF, SF);
}

// round 9
// speedup vs baseline: 2.0199x; 1.2542x over previous
#include <cuda_runtime.h>
#include <cuda_bf16.h>
#include <cstdint>
#include <cstddef>

// Problem constants
#define B_  32
#define S_  2048
#define F_  512
#define MOMENTUM 0.1f
#define EPS 1e-5f

// ---------------- device scratch (static, no allocations) ----------------
__device__ float g_xn   [(size_t)B_ * S_ * F_];   // 128 MB  centered input
__device__ float g_sigma[(size_t)B_ * F_ * F_];
__device__ float g_P    [(size_t)B_ * F_ * F_];
__device__ float g_Q    [(size_t)B_ * F_ * F_];
__device__ float g_T1   [(size_t)B_ * F_ * F_];
__device__ float g_T2   [(size_t)B_ * F_ * F_];
__device__ float g_mean [B_ * F_];
__device__ float g_invtr[B_];
__device__ float g_rstr [B_];

// ---------------- elementwise kernels ----------------
__global__ void mean_kernel(const float* __restrict__ x,
                            const float* __restrict__ rm,
                            float* __restrict__ mean) {
    int b = blockIdx.x;
    int f = threadIdx.x;
    const float* xb = x + (size_t)b * S_ * F_ + f;
    float acc = 0.f;
    #pragma unroll 8
    for (int s = 0; s < S_; s++) acc += xb[(size_t)s * F_];
    mean[b * F_ + f] = (1.f - MOMENTUM) * rm[f] + MOMENTUM * (acc * (1.f / (float)S_));
}

__global__ void xn_kernel(const float* __restrict__ x,
                          const float* __restrict__ mean,
                          float* __restrict__ xn) {
    size_t p4 = (size_t)blockIdx.x * blockDim.x + threadIdx.x;
    size_t p  = p4 * 4;
    int b = (int)(p >> 20);            // S*F = 2^20
    int f = (int)(p & (F_ - 1));
    float4 xv = *(const float4*)(x + p);
    float4 mv = *(const float4*)(mean + b * F_ + f);
    float4 o;
    o.x = xv.x - mv.x; o.y = xv.y - mv.y; o.z = xv.z - mv.z; o.w = xv.w - mv.w;
    *(float4*)(xn + p) = o;
}

__global__ void trace_kernel(const float* __restrict__ sigma,
                             float* __restrict__ invtr,
                             float* __restrict__ rstr) {
    __shared__ float red[512];
    int b = blockIdx.x, t = threadIdx.x;
    red[t] = sigma[(size_t)b * F_ * F_ + (size_t)t * (F_ + 1)];
    __syncthreads();
    for (int s = 256; s > 0; s >>= 1) {
        if (t < s) red[t] += red[t + s];
        __syncthreads();
    }
    if (t == 0) {
        float tr = red[0];
        invtr[b] = 1.f / tr;
        rstr[b]  = 1.f / sqrtf(tr);
    }
}

__global__ void initp_kernel(const float* __restrict__ sigma,
                             const float* __restrict__ invtr,
                             float* __restrict__ P) {
    size_t idx = (size_t)blockIdx.x * blockDim.x + threadIdx.x;
    int b = (int)(idx >> 18);
    int r = (int)((idx >> 9) & (F_ - 1));
    int c = (int)(idx & (F_ - 1));
    float v = -0.5f * invtr[b] * sigma[idx];
    if (r == c) v += 1.5f;
    P[idx] = v;
}

// ---------------- helpers ----------------
__device__ __forceinline__ void cp_async16(void* smem_dst, const void* gmem_src) {
    uint32_t s = (uint32_t)__cvta_generic_to_shared(smem_dst);
    asm volatile("cp.async.cg.shared.global [%0], [%1], 16;\n" :: "r"(s), "l"(gmem_src));
}
#define CP_COMMIT asm volatile("cp.async.commit_group;" ::: "memory")
#define CP_WAIT1  asm volatile("cp.async.wait_group 1;"  ::: "memory")
#define CP_WAIT0  asm volatile("cp.async.wait_group 0;"  ::: "memory")

// split fp32 pair into packed bf16 hi / bf16 lo (x -> lower 16 bits)
__device__ __forceinline__ void split2_bf16(float x, float y, uint32_t& h, uint32_t& l) {
    __nv_bfloat16 hx = __float2bfloat16_rn(x);
    __nv_bfloat16 hy = __float2bfloat16_rn(y);
    float rx = x - __bfloat162float(hx);
    float ry = y - __bfloat162float(hy);
    __nv_bfloat16 lx = __float2bfloat16_rn(rx);
    __nv_bfloat16 ly = __float2bfloat16_rn(ry);
    __nv_bfloat162 hp = __halves2bfloat162(hx, hy);
    __nv_bfloat162 lp = __halves2bfloat162(lx, ly);
    h = *(uint32_t*)&hp;
    l = *(uint32_t*)&lp;
}

__device__ __forceinline__ void mma_bf16(float* c, const uint32_t* a, const uint32_t* b) {
    asm volatile(
        "mma.sync.aligned.m16n8k16.row.col.f32.bf16.bf16.f32 "
        "{%0,%1,%2,%3}, {%4,%5,%6,%7}, {%8,%9}, {%0,%1,%2,%3};"
        : "+f"(c[0]), "+f"(c[1]), "+f"(c[2]), "+f"(c[3])
        : "r"(a[0]), "r"(a[1]), "r"(a[2]), "r"(a[3]), "r"(b[0]), "r"(b[1]));
}

// ---------------- bf16x3 tensor-core GEMM ----------------
// C[M,N] = A @ B. TRANSA: A global is KxM row-major. TRI: triangular grid over
// 128-blocks with mirror stores (C symmetric).
// mode 0: C = AB
// mode 1: C = 1.5*D - 0.5*scale[b]*AB
// mode 2: C = scale[b]*AB
// mode 3: C = 0.9*E + 0.1*(AB/(S-1) + eps*I)   (E has no batch stride)
// Pipeline per 32-K chunk: cp.async fp32 stage (double buffered) -> convert
// pass (split once per element to packed-bf16 hi/lo smem, B transposed) ->
// pure LDS+HMMA mainloop on m16n8k16 fragments.
//
// fp32 stages: A [128][36] (or [32][132] transA), B [32][132]. 36864 B/stage.
// bf16 arrays: Ah/Al/Bh/Bl each [128 rows][32 k] stride 40 bf16 = 10240 B.
#define STG_FP32_B 36864
#define OFF_BF     (2 * STG_FP32_B)          // 73728
#define BF_STAGE_B 40960                     // Ah+Al+Bh+Bl
#define GEMM_SMEM_TOTAL (OFF_BF + 2 * BF_STAGE_B)   // 155648

template<int TRANSA, int TRI>
__global__ __launch_bounds__(256) void gemm_bf16x3_kernel(
        const float* __restrict__ Ag, const float* __restrict__ Bg,
        float* __restrict__ Cg, const float* __restrict__ Dg,
        const float* __restrict__ Eg, const float* __restrict__ scale,
        int M, int N, int K, int mode,
        size_t sAb, size_t sBb, size_t sCb) {
    extern __shared__ char smem[];

    int bz = blockIdx.z;
    const float* A = Ag + (size_t)bz * sAb;
    const float* Bm = Bg + (size_t)bz * sBb;
    float* C = Cg + (size_t)bz * sCb;

    int m0, n0;
    bool mirror = false;
    if (TRI) {
        int t = blockIdx.x;   // 0..9
        int bi = (t < 4) ? 0 : (t < 7) ? 1 : (t < 9) ? 2 : 3;
        int start = (bi == 0) ? 0 : (bi == 1) ? 4 : (bi == 2) ? 7 : 9;
        int bj = bi + (t - start);
        m0 = bi * 128; n0 = bj * 128;
        mirror = (bi != bj);
    } else {
        m0 = blockIdx.y * 128;
        n0 = blockIdx.x * 128;
    }

    int tid  = threadIdx.x;
    int lane = tid & 31;
    int wid  = tid >> 5;
    int warp_m = (wid >> 2) * 64;     // 0 or 64
    int warp_n = (wid & 3) * 32;      // 0,32,64,96
    int g  = lane >> 2;               // 0..7
    int tg = lane & 3;                // 0..3

    float acc[4][4][4];
    #pragma unroll
    for (int i = 0; i < 4; i++)
        #pragma unroll
        for (int j = 0; j < 4; j++)
            #pragma unroll
            for (int q = 0; q < 4; q++) acc[i][j][q] = 0.f;

    // ---- cp.async staging of fp32 tiles ----
    auto prefetch = [&](int st, int k0) {
        float* sA = (float*)(smem + st * STG_FP32_B);
        float* sB = sA + 4608;
        if (!TRANSA) {
            // A: MxK row-major -> sA[m][k], stride 36
            #pragma unroll
            for (int p = 0; p < 4; p++) {
                int c = tid + p * 256;
                int m = c >> 3;
                int kc = (c & 7) * 4;
                cp_async16(sA + m * 36 + kc, A + (size_t)(m0 + m) * K + k0 + kc);
            }
        } else {
            // A: KxM row-major -> sA[k][m], stride 132
            #pragma unroll
            for (int p = 0; p < 4; p++) {
                int c = tid + p * 256;
                int k = c >> 5;
                int mc = (c & 31) * 4;
                cp_async16(sA + k * 132 + mc, A + (size_t)(k0 + k) * M + m0 + mc);
            }
        }
        // B: KxN row-major -> sB[k][n], stride 132
        #pragma unroll
        for (int p = 0; p < 4; p++) {
            int c = tid + p * 256;
            int k = c >> 5;
            int nc = (c & 31) * 4;
            cp_async16(sB + k * 132 + nc, Bm + (size_t)(k0 + k) * N + n0 + nc);
        }
    };

    prefetch(0, 0);
    CP_COMMIT;

    const int NC = K >> 5;
    const int mrow = tid >> 1;             // 0..127
    const int ks   = (tid & 1) * 16;       // 0 or 16

    for (int c = 0; c < NC; c++) {
        int bsel = c & 1;
        if (c + 1 < NC) {
            prefetch(bsel ^ 1, (c + 1) * 32);
            CP_COMMIT;
            CP_WAIT1;
        } else {
            CP_WAIT0;
        }
        __syncthreads();

        // ---- convert: fp32 stage -> packed bf16 hi/lo (B transposed) ----
        {
            const float* fA = (const float*)(smem + bsel * STG_FP32_B);
            const float* fB = fA + 4608;
            char* bf = smem + OFF_BF + bsel * BF_STAGE_B;
            uint32_t* dAh = (uint32_t*)(bf +      0 + (size_t)(mrow * 40 + ks) * 2);
            uint32_t* dAl = (uint32_t*)(bf +  10240 + (size_t)(mrow * 40 + ks) * 2);
            uint32_t* dBh = (uint32_t*)(bf +  20480 + (size_t)(mrow * 40 + ks) * 2);
            uint32_t* dBl = (uint32_t*)(bf +  30720 + (size_t)(mrow * 40 + ks) * 2);
            if (!TRANSA) {
                const float* s = fA + mrow * 36 + ks;
                #pragma unroll
                for (int u = 0; u < 4; u++) {
                    float4 v = *(const float4*)(s + 4 * u);
                    uint32_t h0, l0, h1, l1;
                    split2_bf16(v.x, v.y, h0, l0);
                    split2_bf16(v.z, v.w, h1, l1);
                    dAh[2 * u] = h0; dAh[2 * u + 1] = h1;
                    dAl[2 * u] = l0; dAl[2 * u + 1] = l1;
                }
            } else {
                const float* s = fA + mrow;      // [k][132]
                #pragma unroll
                for (int u = 0; u < 8; u++) {
                    float v0 = s[(ks + 2 * u) * 132];
                    float v1 = s[(ks + 2 * u + 1) * 132];
                    uint32_t h, l;
                    split2_bf16(v0, v1, h, l);
                    dAh[u] = h; dAl[u] = l;
                }
            }
            // B transpose convert
            const float* s = fB + mrow;          // [k][132], col = mrow
            #pragma unroll
            for (int u = 0; u < 8; u++) {
                float v0 = s[(ks + 2 * u) * 132];
                float v1 = s[(ks + 2 * u + 1) * 132];
                uint32_t h, l;
                split2_bf16(v0, v1, h, l);
                dBh[u] = h; dBl[u] = l;
            }
        }
        __syncthreads();

        // ---- compute: 2 k-steps of 16 ----
        const char* bf = smem + OFF_BF + bsel * BF_STAGE_B;
        const char* Ah = bf;
        const char* Al = bf + 10240;
        const char* Bh = bf + 20480;
        const char* Bl = bf + 30720;
        #pragma unroll
        for (int kk = 0; kk < 32; kk += 16) {
            int kf = kk + 2 * tg;
            uint32_t bh[4][2], bl[4][2];
            #pragma unroll
            for (int j = 0; j < 4; j++) {
                int col = warp_n + j * 8 + g;
                bh[j][0] = *(const uint32_t*)(Bh + (size_t)(col * 40 + kf) * 2);
                bh[j][1] = *(const uint32_t*)(Bh + (size_t)(col * 40 + kf + 8) * 2);
                bl[j][0] = *(const uint32_t*)(Bl + (size_t)(col * 40 + kf) * 2);
                bl[j][1] = *(const uint32_t*)(Bl + (size_t)(col * 40 + kf + 8) * 2);
            }
            #pragma unroll
            for (int i = 0; i < 4; i++) {
                int row = warp_m + i * 16;
                uint32_t ah[4], al[4];
                ah[0] = *(const uint32_t*)(Ah + (size_t)((row + g) * 40 + kf) * 2);
                ah[1] = *(const uint32_t*)(Ah + (size_t)((row + g + 8) * 40 + kf) * 2);
                ah[2] = *(const uint32_t*)(Ah + (size_t)((row + g) * 40 + kf + 8) * 2);
                ah[3] = *(const uint32_t*)(Ah + (size_t)((row + g + 8) * 40 + kf + 8) * 2);
                al[0] = *(const uint32_t*)(Al + (size_t)((row + g) * 40 + kf) * 2);
                al[1] = *(const uint32_t*)(Al + (size_t)((row + g + 8) * 40 + kf) * 2);
                al[2] = *(const uint32_t*)(Al + (size_t)((row + g) * 40 + kf + 8) * 2);
                al[3] = *(const uint32_t*)(Al + (size_t)((row + g + 8) * 40 + kf + 8) * 2);
                #pragma unroll
                for (int j = 0; j < 4; j++) {
                    mma_bf16(acc[i][j], ah, bh[j]);   // hi*hi
                    mma_bf16(acc[i][j], ah, bl[j]);   // hi*lo
                    mma_bf16(acc[i][j], al, bh[j]);   // lo*hi
                }
            }
        }
        __syncthreads();
    }

    // ---- epilogue ----
    float sc = 0.f;
    if (mode == 1) sc = -0.5f * scale[bz];
    else if (mode == 2) sc = scale[bz];
    const float* D = (mode == 1) ? (Dg + (size_t)bz * sCb) : nullptr;
    const float inv_nm1 = 1.f / (float)(S_ - 1);

    #pragma unroll
    for (int i = 0; i < 4; i++) {
        #pragma unroll
        for (int j = 0; j < 4; j++) {
            int r0 = m0 + warp_m + i * 16 + g;
            int c0 = n0 + warp_n + j * 8 + 2 * tg;
            #pragma unroll
            for (int half = 0; half < 2; half++) {
                int r = r0 + half * 8;
                float v0 = acc[i][j][half * 2 + 0];
                float v1 = acc[i][j][half * 2 + 1];
                size_t off = (size_t)r * N + c0;
                float2 o;
                if (mode == 0) {
                    o.x = v0; o.y = v1;
                } else if (mode == 1) {
                    o.x = 1.5f * D[off] + sc * v0;
                    o.y = 1.5f * D[off + 1] + sc * v1;
                } else if (mode == 2) {
                    o.x = sc * v0; o.y = sc * v1;
                } else {
                    float s0 = v0 * inv_nm1 + ((r == c0)     ? EPS : 0.f);
                    float s1 = v1 * inv_nm1 + ((r == c0 + 1) ? EPS : 0.f);
                    o.x = (1.f - MOMENTUM) * Eg[off] + MOMENTUM * s0;
                    o.y = (1.f - MOMENTUM) * Eg[off + 1] + MOMENTUM * s1;
                }
                *(float2*)(C + off) = o;
                if (TRI && mirror) {
                    C[(size_t)c0 * N + r]       = o.x;
                    C[(size_t)(c0 + 1) * N + r] = o.y;
                }
            }
        }
    }
}

// ---------------- host launcher ----------------
extern "C" void kernel_launch(void* const* d_in, const int* in_sizes, int n_in,
                              void* d_out, int out_size) {
    const float* x  = (const float*)d_in[0];
    const float* rm = (const float*)d_in[1];
    const float* rc = (const float*)d_in[2];
    float* out = (float*)d_out;

    float *xn, *sigma, *P, *Q, *T1, *T2, *mean, *invtr, *rstr;
    cudaGetSymbolAddress((void**)&xn,    g_xn);
    cudaGetSymbolAddress((void**)&sigma, g_sigma);
    cudaGetSymbolAddress((void**)&P,     g_P);
    cudaGetSymbolAddress((void**)&Q,     g_Q);
    cudaGetSymbolAddress((void**)&T1,    g_T1);
    cudaGetSymbolAddress((void**)&T2,    g_T2);
    cudaGetSymbolAddress((void**)&mean,  g_mean);
    cudaGetSymbolAddress((void**)&invtr, g_invtr);
    cudaGetSymbolAddress((void**)&rstr,  g_rstr);

    static bool attr_set = false;
    if (!attr_set) {
        cudaFuncSetAttribute(gemm_bf16x3_kernel<0,0>,
            cudaFuncAttributeMaxDynamicSharedMemorySize, GEMM_SMEM_TOTAL);
        cudaFuncSetAttribute(gemm_bf16x3_kernel<0,1>,
            cudaFuncAttributeMaxDynamicSharedMemorySize, GEMM_SMEM_TOTAL);
        cudaFuncSetAttribute(gemm_bf16x3_kernel<1,1>,
            cudaFuncAttributeMaxDynamicSharedMemorySize, GEMM_SMEM_TOTAL);
        attr_set = true;
    }

    const size_t FF = (size_t)F_ * F_;
    const size_t SF = (size_t)S_ * F_;

    // 1. blended mean
    mean_kernel<<<B_, F_>>>(x, rm, mean);
    // 2. xn = x - m
    xn_kernel<<<(unsigned)((size_t)B_ * SF / 4 / 256), 256>>>(x, mean, xn);
    // 3. sigma = 0.9*rc + 0.1*(xn^T xn /(S-1) + eps*I)  [transA SYRK, triangular]
    gemm_bf16x3_kernel<1,1><<<dim3(10, 1, B_), 256, GEMM_SMEM_TOTAL>>>(
        xn, xn, sigma, nullptr, rc, nullptr, F_, F_, S_, 3, SF, SF, FF);
    // 4. trace
    trace_kernel<<<B_, F_>>>(sigma, invtr, rstr);
    // 5. P1 = 1.5I - 0.5 sigma/tr
    initp_kernel<<<(unsigned)((size_t)B_ * FF / 256), 256>>>(sigma, invtr, P);

    // 6. NS iterations 2..4 (all products symmetric: polynomials in sigma)
    float* Pin = P;
    float* Pout = Q;
    for (int it = 0; it < 3; it++) {
        gemm_bf16x3_kernel<0,1><<<dim3(10, 1, B_), 256, GEMM_SMEM_TOTAL>>>(
            Pin, Pin, T1, nullptr, nullptr, nullptr, F_, F_, F_, 0, FF, FF, FF);
        gemm_bf16x3_kernel<0,1><<<dim3(10, 1, B_), 256, GEMM_SMEM_TOTAL>>>(
            T1, Pin, T2, nullptr, nullptr, nullptr, F_, F_, F_, 0, FF, FF, FF);
        gemm_bf16x3_kernel<0,1><<<dim3(10, 1, B_), 256, GEMM_SMEM_TOTAL>>>(
            T2, sigma, Pout, Pin, nullptr, invtr, F_, F_, F_, 1, FF, FF, FF);
        float* tmp = Pin; Pin = Pout; Pout = tmp;
    }

    // 7. out = (xn @ P) * rsqrt(tr)
    gemm_bf16x3_kernel<0,0><<<dim3(4, 16, B_), 256, GEMM_SMEM_TOTAL>>>(
        xn, Pin, out, nullptr, nullptr, rstr, S_, F_, F_, 2, SF, FF, SF);
}